// round 1
// baseline (speedup 1.0000x reference)
#include <cuda_runtime.h>
#include <cstdint>

// Problem constants
#define Bc 2
#define Hc 8
#define Nc 2048
#define Pc 64
#define Mc 4
#define Dc 256
#define NX (2*Nc)   // 4096 rows of X = concat(Q,K)

// Tiling
#define BN 128      // n rows per CTA
#define BC 128      // packed columns per CTA: c = d'*4 + m  (BD=32 d's x 4 m's)
#define BD 32
#define KP 64       // K dim = P, fully resident
#define TH 256
#define PAD 4
#define LDA (BN + PAD)   // 132 floats: 16B-aligned row stride, bounded bank conflicts
#define LDW (BC + PAD)

__global__ void __launch_bounds__(TH) sketch_attn_kernel(
    const float* __restrict__ Q, const float* __restrict__ Km,
    const int* __restrict__ sk, const float* __restrict__ sgn,
    float* __restrict__ out)
{
    extern __shared__ float smem[];
    float* As = smem;               // [KP][LDA]  X tile, transposed: As[p][n]
    float* Ws = smem + KP * LDA;    // [KP][LDW]  gathered W tile:    Ws[p][c]

    const int bh = blockIdx.z;
    const int b  = bh >> 3;
    const int h  = bh & 7;
    const int n0 = blockIdx.x * BN;
    const int d0 = blockIdx.y * BD;
    const int tid = threadIdx.x;

    const float* Xq = Q  + (size_t)(b * Hc + h) * Nc * Pc;
    const float* Xk = Km + (size_t)(b * Hc + h) * Nc * Pc;

    // ---- Load X tile (128 rows x 64) into As[p][n]; global reads coalesced over p ----
    for (int i = tid; i < BN * KP; i += TH) {
        int n = i >> 6;          // i / 64
        int p = i & 63;
        int gn = n0 + n;
        const float* src = (gn < Nc) ? (Xq + (size_t)gn * Pc)
                                     : (Xk + (size_t)(gn - Nc) * Pc);
        As[p * LDA + n] = src[p];
    }

    // ---- Gather W tile: row c -> (m = c&3, d = d0 + c>>2); source row s = sketch[b,m,d] ----
    for (int i = tid; i < BC * KP; i += TH) {
        int c = i >> 6;
        int p = i & 63;
        int m = c & 3;
        int d = d0 + (c >> 2);
        int s = sk[(b * Mc + m) * Dc + d];          // s in [0, 2N)
        const float* src = (s < Nc) ? (Xq + (size_t)s * Pc)
                                    : (Xk + (size_t)(s - Nc) * Pc);
        Ws[p * LDW + c] = src[p];
    }
    __syncthreads();

    // ---- 8x8 register microtile GEMM over p = 0..63 ----
    const int tx = tid & 15;
    const int ty = tid >> 4;
    const int na = ty * 8;
    const int ca = tx * 8;

    float acc[8][8];
    #pragma unroll
    for (int i = 0; i < 8; i++)
        #pragma unroll
        for (int j = 0; j < 8; j++)
            acc[i][j] = 0.0f;

    #pragma unroll 8
    for (int p = 0; p < KP; p++) {
        float4 a0 = *(const float4*)(As + p * LDA + na);
        float4 a1 = *(const float4*)(As + p * LDA + na + 4);
        float4 w0 = *(const float4*)(Ws + p * LDW + ca);
        float4 w1 = *(const float4*)(Ws + p * LDW + ca + 4);
        float av[8] = {a0.x, a0.y, a0.z, a0.w, a1.x, a1.y, a1.z, a1.w};
        float wv[8] = {w0.x, w0.y, w0.z, w0.w, w1.x, w1.y, w1.z, w1.w};
        #pragma unroll
        for (int i = 0; i < 8; i++)
            #pragma unroll
            for (int j = 0; j < 8; j++)
                acc[i][j] = fmaf(av[i], wv[j], acc[i][j]);
    }

    // ---- Epilogue: thread-local exp + signed m-reduction; 8 rows x 2 d's per thread ----
    const int dd = d0 + tx * 2;     // thread's two consecutive d columns (even -> 8B aligned)
    float s0[4], s1[4];
    #pragma unroll
    for (int m = 0; m < 4; m++) {
        s0[m] = sgn[m * Dc + dd];
        s1[m] = sgn[m * Dc + dd + 1];
    }

    #pragma unroll
    for (int i = 0; i < 8; i++) {
        int gn = n0 + na + i;
        float r0 = 0.0f, r1 = 0.0f;
        #pragma unroll
        for (int m = 0; m < 4; m++) {
            r0 += s0[m] * __expf(acc[i][m]);       // c = j,   j=0..3 -> (dd,   m=j)
            r1 += s1[m] * __expf(acc[i][4 + m]);   // c = 4+j, j=0..3 -> (dd+1, m=j)
        }
        float2 v = make_float2(r0, r1);
        *(float2*)(out + ((size_t)bh * NX + gn) * Dc + dd) = v;
    }
}

extern "C" void kernel_launch(void* const* d_in, const int* in_sizes, int n_in,
                              void* d_out, int out_size)
{
    const float* Q  = (const float*)d_in[0];
    const float* K  = (const float*)d_in[1];
    const int*   sk = (const int*)d_in[2];
    const float* sg = (const float*)d_in[3];
    float* out = (float*)d_out;

    size_t smem = (size_t)(KP * LDA + KP * LDW) * sizeof(float);  // 67,584 B
    cudaFuncSetAttribute(sketch_attn_kernel,
                         cudaFuncAttributeMaxDynamicSharedMemorySize, (int)smem);

    dim3 grid(NX / BN, Dc / BD, Bc * Hc);   // (32, 8, 16) = 4096 CTAs
    sketch_attn_kernel<<<grid, TH, smem>>>(Q, K, sk, sg, out);
}

// round 2
// speedup vs baseline: 1.6525x; 1.6525x over previous
#include <cuda_runtime.h>
#include <cstdint>

// Problem constants
#define Bc 2
#define Hc 8
#define Nc 2048
#define Pc 64
#define Mc 4
#define Dc 256
#define NX (2*Nc)    // 4096 rows of X = concat(Q,K)

// Tiling
#define BN 128       // n rows per CTA
#define BC 128       // packed columns per CTA: c = d'*4 + m (32 d's x 4 m's)
#define TH 256
#define LDT 68       // smem row stride (floats): 68 % 32 == 4 -> conflict-free frags

__device__ __forceinline__ uint32_t f2tf32(float x) {
    uint32_t r;
    asm("cvt.rna.tf32.f32 %0, %1;" : "=r"(r) : "f"(x));
    return r;
}

__global__ void __launch_bounds__(TH) sketch_attn_tf32(
    const float* __restrict__ Q, const float* __restrict__ Km,
    const int* __restrict__ sk, const float* __restrict__ sgn,
    float* __restrict__ out)
{
    extern __shared__ uint32_t smem[];
    uint32_t* As = smem;             // [BN][LDT]  X tile (row-major n x p), tf32 bits
    uint32_t* Ws = smem + BN * LDT;  // [BC][LDT]  gathered W tile (c x p), tf32 bits

    const int bh = blockIdx.z;
    const int b  = bh >> 3;
    const int n0 = blockIdx.x * BN;
    const int d0 = blockIdx.y * 32;         // 32 d-columns per CTA
    const int tid = threadIdx.x;

    const float* Xq = Q  + (size_t)bh * Nc * Pc;
    const float* Xk = Km + (size_t)bh * Nc * Pc;

    // ---- Fill X tile: As[n][p], coalesced over p ----
    for (int i = tid; i < BN * Pc; i += TH) {
        int n = i >> 6, p = i & 63;
        int gn = n0 + n;
        const float* src = (gn < Nc) ? (Xq + (size_t)gn * Pc)
                                     : (Xk + (size_t)(gn - Nc) * Pc);
        As[n * LDT + p] = f2tf32(src[p]);
    }

    // ---- Gather W tile: row c -> (m = c&3, d = d0 + c>>2), source row sk[b,m,d] ----
    for (int i = tid; i < BC * Pc; i += TH) {
        int c = i >> 6, p = i & 63;
        int m = c & 3;
        int d = d0 + (c >> 2);
        int s = sk[(b * Mc + m) * Dc + d];
        const float* src = (s < Nc) ? (Xq + (size_t)s * Pc)
                                    : (Xk + (size_t)(s - Nc) * Pc);
        Ws[c * LDT + p] = f2tf32(src[p]);
    }
    __syncthreads();

    // ---- Warp tiling: 2 (n) x 4 (c) warps; warp tile = 64 x 32 ----
    const int lane = tid & 31, warp = tid >> 5;
    const int wn = warp & 1, wc = warp >> 1;
    const int na = wn * 64, ca = wc * 32;
    const int g = lane >> 2, q = lane & 3;

    float acc[4][4][4];
    #pragma unroll
    for (int i = 0; i < 4; i++)
        #pragma unroll
        for (int j = 0; j < 4; j++)
            #pragma unroll
            for (int r = 0; r < 4; r++)
                acc[i][j][r] = 0.0f;

    // ---- K-loop: 8 steps of m16n8k8 tf32, 4x4 mma grid per warp ----
    #pragma unroll
    for (int k = 0; k < 8; k++) {
        const int kc = k * 8 + q;
        uint32_t a[4][4];
        #pragma unroll
        for (int i = 0; i < 4; i++) {
            const uint32_t* ab = As + (na + i * 16 + g) * LDT + kc;
            a[i][0] = ab[0];            // (row g,    col q)
            a[i][1] = ab[8 * LDT];      // (row g+8,  col q)
            a[i][2] = ab[4];            // (row g,    col q+4)
            a[i][3] = ab[8 * LDT + 4];  // (row g+8,  col q+4)
        }
        uint32_t bb[4][2];
        #pragma unroll
        for (int j = 0; j < 4; j++) {
            const uint32_t* wb = Ws + (ca + j * 8 + g) * LDT + kc;
            bb[j][0] = wb[0];           // (k q,   n g)
            bb[j][1] = wb[4];           // (k q+4, n g)
        }
        #pragma unroll
        for (int i = 0; i < 4; i++)
            #pragma unroll
            for (int j = 0; j < 4; j++)
                asm volatile(
                    "mma.sync.aligned.m16n8k8.row.col.f32.tf32.tf32.f32 "
                    "{%0,%1,%2,%3}, {%4,%5,%6,%7}, {%8,%9}, {%0,%1,%2,%3};\n"
                    : "+f"(acc[i][j][0]), "+f"(acc[i][j][1]),
                      "+f"(acc[i][j][2]), "+f"(acc[i][j][3])
                    : "r"(a[i][0]), "r"(a[i][1]), "r"(a[i][2]), "r"(a[i][3]),
                      "r"(bb[j][0]), "r"(bb[j][1]));
    }

    // ---- Epilogue: exp + signed m-reduction ----
    // Thread's two C-columns (2q, 2q+1) share d; lane pair (q xor 1) holds the
    // other two m's for the same d -> shfl_xor(1) completes the 4-way sum.
    const int m0 = (q & 1) * 2;
    #pragma unroll
    for (int j = 0; j < 4; j++) {
        const int d = d0 + wc * 8 + j * 2 + (q >> 1);
        const float sA = sgn[m0 * Dc + d];
        const float sB = sgn[(m0 + 1) * Dc + d];
        #pragma unroll
        for (int i = 0; i < 4; i++) {
            float e0 = sA * __expf(acc[i][j][0]) + sB * __expf(acc[i][j][1]); // row g
            float e1 = sA * __expf(acc[i][j][2]) + sB * __expf(acc[i][j][3]); // row g+8
            e0 += __shfl_xor_sync(0xffffffffu, e0, 1);
            e1 += __shfl_xor_sync(0xffffffffu, e1, 1);
            if ((q & 1) == 0) {
                const int n = n0 + na + i * 16 + g;
                out[((size_t)bh * NX + n) * Dc + d]     = e0;
                out[((size_t)bh * NX + n + 8) * Dc + d] = e1;
            }
        }
    }
}

extern "C" void kernel_launch(void* const* d_in, const int* in_sizes, int n_in,
                              void* d_out, int out_size)
{
    const float* Q  = (const float*)d_in[0];
    const float* K  = (const float*)d_in[1];
    const int*   sk = (const int*)d_in[2];
    const float* sg = (const float*)d_in[3];
    float* out = (float*)d_out;

    size_t smem = (size_t)(BN + BC) * LDT * sizeof(uint32_t);  // 69,632 B
    cudaFuncSetAttribute(sketch_attn_tf32,
                         cudaFuncAttributeMaxDynamicSharedMemorySize, (int)smem);

    dim3 grid(NX / BN, Dc / 32, Bc * Hc);   // (32, 8, 16) = 4096 CTAs
    sketch_attn_tf32<<<grid, TH, smem>>>(Q, K, sk, sg, out);
}

// round 4
// speedup vs baseline: 2.1205x; 1.2832x over previous
#include <cuda_runtime.h>
#include <cuda_bf16.h>
#include <cstdint>

// Problem constants
#define Bc 2
#define Hc 8
#define Nc 2048
#define Pc 64
#define Mc 4
#define Dc 256
#define NX 4096

// Tiling: per CTA C = X(128x64) * W^T(128x64) -> 128x128, cols packed c = d'*4 + m
#define BN 128
#define BC 128
#define TH 256
#define LDH 72          // smem row stride in bf16 elems (144 B): LDSM conflict-free
#define ROWB 144        // row stride bytes
#define OFF_A 0
#define OFF_B (BN * ROWB)             // 18,432
#define SMEM_BYTES (2 * BN * ROWB)    // 36,864

__device__ __forceinline__ uint32_t s2u(const void* p) {
    uint32_t a;
    asm("{ .reg .u64 t; cvta.to.shared.u64 t, %1; cvt.u32.u64 %0, t; }" : "=r"(a) : "l"(p));
    return a;
}
__device__ __forceinline__ uint32_t pack_bf16x2(float lo, float hi) {
    uint32_t r;
    asm("cvt.rn.bf16x2.f32 %0, %1, %2;" : "=r"(r) : "f"(hi), "f"(lo));
    return r;
}

__global__ void __launch_bounds__(TH) sketch_attn_bf16(
    const float* __restrict__ Q, const float* __restrict__ Km,
    const int* __restrict__ sk, const float* __restrict__ sgn,
    float* __restrict__ out)
{
    extern __shared__ char smem[];
    const uint32_t sb = s2u(smem);
    const int tid = threadIdx.x;

    const int bh = blockIdx.z;
    const int b  = bh >> 3;
    const int n0 = blockIdx.x * BN;
    const int d0 = blockIdx.y * 32;

    const float* Xq = Q  + (size_t)bh * Nc * Pc;
    const float* Xk = Km + (size_t)bh * Nc * Pc;

    // ---- Fill A tile: X rows n0..+127, float4 load -> bf16x2 pair store (8 B) ----
    for (int i = tid; i < BN * (Pc / 4); i += TH) {
        int r = i >> 4, v = (i & 15) << 2;
        int gn = n0 + r;
        const float* src = (gn < Nc) ? (Xq + (size_t)gn * Pc)
                                     : (Xk + (size_t)(gn - Nc) * Pc);
        float4 x = *(const float4*)(src + v);
        uint2 y = make_uint2(pack_bf16x2(x.x, x.y), pack_bf16x2(x.z, x.w));
        *(uint2*)(smem + OFF_A + r * ROWB + v * 2) = y;
    }
    // ---- Gather W tile: packed row c -> (m = c&3, d = d0 + c>>2), src row sk[b,m,d] ----
    for (int i = tid; i < BC * (Pc / 4); i += TH) {
        int c = i >> 4, v = (i & 15) << 2;
        int m = c & 3;
        int d = d0 + (c >> 2);
        int s = sk[(b * Mc + m) * Dc + d];
        const float* src = (s < Nc) ? (Xq + (size_t)s * Pc)
                                    : (Xk + (size_t)(s - Nc) * Pc);
        float4 x = *(const float4*)(src + v);
        uint2 y = make_uint2(pack_bf16x2(x.x, x.y), pack_bf16x2(x.z, x.w));
        *(uint2*)(smem + OFF_B + c * ROWB + v * 2) = y;
    }
    __syncthreads();

    // ---- Warp tiling: 2 (n) x 4 (c) warps; warp tile 64 x 32 ----
    const int lane = tid & 31, warp = tid >> 5;
    const int wn = warp & 1, wc = warp >> 1;
    const int na = wn * 64, ca = wc * 32;
    const int g = lane >> 2, q = lane & 3;

    // LDSM lane addresses.
    // A x4 (one 16x16 tile): lanes 0-7 rows 0-7 lo-half, 8-15 rows 8-15 lo,
    //                        16-23 rows 0-7 hi-half, 24-31 rows 8-15 hi.
    const uint32_t aAddr = sb + OFF_A
        + (uint32_t)(na + (lane & 15)) * ROWB + (uint32_t)(lane >> 4) * 16;
    // B x4 (two 8x16 tiles j, j+1): lanes 0-7 (j, klo), 8-15 (j, khi),
    //                               16-23 (j+1, klo), 24-31 (j+1, khi).
    const uint32_t bAddr = sb + OFF_B
        + (uint32_t)(ca + ((lane >> 4) << 3) + (lane & 7)) * ROWB
        + (uint32_t)((lane >> 3) & 1) * 16;

    float acc[4][4][4];
    #pragma unroll
    for (int i = 0; i < 4; i++)
        #pragma unroll
        for (int j = 0; j < 4; j++)
            #pragma unroll
            for (int r = 0; r < 4; r++)
                acc[i][j][r] = 0.0f;

    // ---- K-loop: 4 steps of k16; 4x4 m16n8k16 grid per warp ----
    #pragma unroll
    for (int k = 0; k < 4; k++) {
        const uint32_t ko = (uint32_t)k * 32;   // 16 bf16 cols = 32 B
        uint32_t a[4][4];
        #pragma unroll
        for (int i = 0; i < 4; i++)
            asm volatile("ldmatrix.sync.aligned.m8n8.x4.shared.b16 {%0,%1,%2,%3}, [%4];"
                         : "=r"(a[i][0]), "=r"(a[i][1]), "=r"(a[i][2]), "=r"(a[i][3])
                         : "r"(aAddr + (uint32_t)i * 16 * ROWB + ko));
        uint32_t bb[4][2];
        #pragma unroll
        for (int p = 0; p < 2; p++)
            asm volatile("ldmatrix.sync.aligned.m8n8.x4.shared.b16 {%0,%1,%2,%3}, [%4];"
                         : "=r"(bb[2*p][0]), "=r"(bb[2*p][1]),
                           "=r"(bb[2*p+1][0]), "=r"(bb[2*p+1][1])
                         : "r"(bAddr + (uint32_t)p * 16 * ROWB + ko));
        #pragma unroll
        for (int i = 0; i < 4; i++)
            #pragma unroll
            for (int j = 0; j < 4; j++)
                asm volatile(
                    "mma.sync.aligned.m16n8k16.row.col.f32.bf16.bf16.f32 "
                    "{%0,%1,%2,%3}, {%4,%5,%6,%7}, {%8,%9}, {%0,%1,%2,%3};\n"
                    : "+f"(acc[i][j][0]), "+f"(acc[i][j][1]),
                      "+f"(acc[i][j][2]), "+f"(acc[i][j][3])
                    : "r"(a[i][0]), "r"(a[i][1]), "r"(a[i][2]), "r"(a[i][3]),
                      "r"(bb[j][0]), "r"(bb[j][1]));
    }

    // ---- Epilogue: exp + signed m-reduction (same mapping as tf32 round) ----
    // C fragment: c0,c1 = (row g, cols 2q,2q+1); c2,c3 = (row g+8, cols 2q,2q+1).
    // Cols 2q,2q+1 share d; lane pair (q xor 1) holds the other two m's.
    const int m0 = (q & 1) * 2;
    #pragma unroll
    for (int j = 0; j < 4; j++) {
        const int d = d0 + wc * 8 + j * 2 + (q >> 1);
        const float sA = sgn[m0 * Dc + d];
        const float sB = sgn[(m0 + 1) * Dc + d];
        #pragma unroll
        for (int i = 0; i < 4; i++) {
            float e0 = sA * __expf(acc[i][j][0]) + sB * __expf(acc[i][j][1]); // row g
            float e1 = sA * __expf(acc[i][j][2]) + sB * __expf(acc[i][j][3]); // row g+8
            e0 += __shfl_xor_sync(0xffffffffu, e0, 1);
            e1 += __shfl_xor_sync(0xffffffffu, e1, 1);
            if ((q & 1) == 0) {
                const int n = n0 + na + i * 16 + g;
                out[((size_t)bh * NX + n) * Dc + d]     = e0;
                out[((size_t)bh * NX + n + 8) * Dc + d] = e1;
            }
        }
    }
}

extern "C" void kernel_launch(void* const* d_in, const int* in_sizes, int n_in,
                              void* d_out, int out_size)
{
    const float* Q  = (const float*)d_in[0];
    const float* K  = (const float*)d_in[1];
    const int*   sk = (const int*)d_in[2];
    const float* sg = (const float*)d_in[3];
    float* out = (float*)d_out;

    cudaFuncSetAttribute(sketch_attn_bf16,
                         cudaFuncAttributeMaxDynamicSharedMemorySize, SMEM_BYTES);

    dim3 grid(NX / BN, Dc / 32, Bc * Hc);   // (32, 8, 16) = 4096 CTAs
    sketch_attn_bf16<<<grid, TH, SMEM_BYTES>>>(Q, K, sk, sg, out);
}

// round 5
// speedup vs baseline: 2.7624x; 1.3027x over previous
#include <cuda_runtime.h>
#include <cuda_bf16.h>
#include <cstdint>

// Problem constants
#define Bc 2
#define Hc 8
#define Nc 2048
#define Pc 64
#define Mc 4
#define Dc 256
#define NX 4096

// Tiling: CTA holds X tile (128 x 64); loops over NBLK d-blocks of 32 d's.
// Per block: C = X(128x64) * W^T(128x64) -> 128x128, cols packed c = d'*4 + m.
#define BN 128
#define BC 128
#define NBLK 4
#define TH 256
#define ROWB 144                      // smem row stride bytes (LDSM conflict-free)
#define OFF_A 0
#define OFF_B0 (BN * ROWB)            // 18,432
#define OFF_B1 (OFF_B0 + BC * ROWB)   // 36,864
#define SMEM_BYTES (OFF_B1 + BC * ROWB)  // 55,296 B

__device__ __forceinline__ uint32_t s2u(const void* p) {
    uint32_t a;
    asm("{ .reg .u64 t; cvta.to.shared.u64 t, %1; cvt.u32.u64 %0, t; }" : "=r"(a) : "l"(p));
    return a;
}
__device__ __forceinline__ uint32_t pack_bf16x2(float lo, float hi) {
    uint32_t r;
    asm("cvt.rn.bf16x2.f32 %0, %1, %2;" : "=r"(r) : "f"(hi), "f"(lo));
    return r;
}

__global__ void __launch_bounds__(TH) sketch_attn_pipe(
    const float* __restrict__ Q, const float* __restrict__ Km,
    const int* __restrict__ sk, const float* __restrict__ sgn,
    float* __restrict__ out)
{
    extern __shared__ char smem[];
    const uint32_t sb = s2u(smem);
    const int tid = threadIdx.x;

    const int bh = blockIdx.z;
    const int b  = bh >> 3;
    const int n0 = blockIdx.x * BN;
    const int dbase = blockIdx.y * (NBLK * 32);   // 128 d's per CTA

    const float* Xq = Q  + (size_t)bh * Nc * Pc;
    const float* Xk = Km + (size_t)bh * Nc * Pc;

    // ---- Fill A tile once: X rows n0..+127 (float4 -> bf16x2 pair) ----
    #pragma unroll
    for (int it = 0; it < (BN * 16) / TH; it++) {
        int i = it * TH + tid;
        int r = i >> 4, v = (i & 15) << 2;
        int gn = n0 + r;
        const float* src = (gn < Nc) ? (Xq + (size_t)gn * Pc)
                                     : (Xk + (size_t)(gn - Nc) * Pc);
        float4 x = *(const float4*)(src + v);
        *(uint2*)(smem + OFF_A + r * ROWB + v * 2) =
            make_uint2(pack_bf16x2(x.x, x.y), pack_bf16x2(x.z, x.w));
    }

    // ---- W gather into a given buffer: row c -> (m = c&3, d = d0 + c>>2) ----
    auto gatherW = [&](int d0, uint32_t off) {
        #pragma unroll
        for (int it = 0; it < (BC * 16) / TH; it++) {
            int i = it * TH + tid;
            int c = i >> 4, v = (i & 15) << 2;
            int m = c & 3;
            int d = d0 + (c >> 2);
            int s = sk[(b * Mc + m) * Dc + d];
            const float* src = (s < Nc) ? (Xq + (size_t)s * Pc)
                                        : (Xk + (size_t)(s - Nc) * Pc);
            float4 x = *(const float4*)(src + v);
            *(uint2*)(smem + (size_t)off + c * ROWB + v * 2) =
                make_uint2(pack_bf16x2(x.x, x.y), pack_bf16x2(x.z, x.w));
        }
    };

    gatherW(dbase, OFF_B0);
    __syncthreads();

    // ---- Warp tiling: 2 (n) x 4 (c) warps; warp tile 64 x 32 ----
    const int lane = tid & 31, warp = tid >> 5;
    const int wn = warp & 1, wc = warp >> 1;
    const int na = wn * 64, ca = wc * 32;
    const int g = lane >> 2, q = lane & 3;
    const int m0 = (q & 1) * 2;

    // LDSM lane addresses (per buffer for B).
    const uint32_t aAddr = sb + OFF_A
        + (uint32_t)(na + (lane & 15)) * ROWB + (uint32_t)(lane >> 4) * 16;
    const uint32_t bLane =
        (uint32_t)(ca + ((lane >> 4) << 3) + (lane & 7)) * ROWB
        + (uint32_t)((lane >> 3) & 1) * 16;
    const uint32_t bAddrs[2] = { sb + OFF_B0 + bLane, sb + OFF_B1 + bLane };
    const uint32_t bufOff[2] = { OFF_B0, OFF_B1 };

    #pragma unroll
    for (int j = 0; j < NBLK; j++) {
        // Prefetch next W block into the idle buffer (overlaps MMA + epilogue).
        if (j < NBLK - 1)
            gatherW(dbase + (j + 1) * 32, bufOff[(j + 1) & 1]);

        const uint32_t bAddr = bAddrs[j & 1];
        const int d0 = dbase + j * 32;

        float acc[4][4][4];
        #pragma unroll
        for (int i = 0; i < 4; i++)
            #pragma unroll
            for (int jj = 0; jj < 4; jj++)
                #pragma unroll
                for (int r = 0; r < 4; r++)
                    acc[i][jj][r] = 0.0f;

        // K-loop: 4 steps of k16; 4x4 m16n8k16 grid per warp.
        #pragma unroll
        for (int k = 0; k < 4; k++) {
            const uint32_t ko = (uint32_t)k * 32;
            uint32_t a[4][4];
            #pragma unroll
            for (int i = 0; i < 4; i++)
                asm volatile("ldmatrix.sync.aligned.m8n8.x4.shared.b16 {%0,%1,%2,%3}, [%4];"
                             : "=r"(a[i][0]), "=r"(a[i][1]), "=r"(a[i][2]), "=r"(a[i][3])
                             : "r"(aAddr + (uint32_t)i * 16 * ROWB + ko));
            uint32_t bb[4][2];
            #pragma unroll
            for (int p = 0; p < 2; p++)
                asm volatile("ldmatrix.sync.aligned.m8n8.x4.shared.b16 {%0,%1,%2,%3}, [%4];"
                             : "=r"(bb[2*p][0]), "=r"(bb[2*p][1]),
                               "=r"(bb[2*p+1][0]), "=r"(bb[2*p+1][1])
                             : "r"(bAddr + (uint32_t)p * 16 * ROWB + ko));
            #pragma unroll
            for (int i = 0; i < 4; i++)
                #pragma unroll
                for (int jj = 0; jj < 4; jj++)
                    asm volatile(
                        "mma.sync.aligned.m16n8k16.row.col.f32.bf16.bf16.f32 "
                        "{%0,%1,%2,%3}, {%4,%5,%6,%7}, {%8,%9}, {%0,%1,%2,%3};\n"
                        : "+f"(acc[i][jj][0]), "+f"(acc[i][jj][1]),
                          "+f"(acc[i][jj][2]), "+f"(acc[i][jj][3])
                        : "r"(a[i][0]), "r"(a[i][1]), "r"(a[i][2]), "r"(a[i][3]),
                          "r"(bb[jj][0]), "r"(bb[jj][1]));
        }

        // Epilogue: exp + signed m-reduction.
        // c0,c1 = (row g, cols 2q,2q+1); c2,c3 = (row g+8, cols 2q,2q+1).
        // Cols 2q,2q+1 share d; lane pair (q xor 1) holds the other two m's.
        #pragma unroll
        for (int jj = 0; jj < 4; jj++) {
            const int d = d0 + wc * 8 + jj * 2 + (q >> 1);
            const float sA = sgn[m0 * Dc + d];
            const float sB = sgn[(m0 + 1) * Dc + d];
            #pragma unroll
            for (int i = 0; i < 4; i++) {
                float e0 = sA * __expf(acc[i][jj][0]) + sB * __expf(acc[i][jj][1]);
                float e1 = sA * __expf(acc[i][jj][2]) + sB * __expf(acc[i][jj][3]);
                e0 += __shfl_xor_sync(0xffffffffu, e0, 1);
                e1 += __shfl_xor_sync(0xffffffffu, e1, 1);
                if ((q & 1) == 0) {
                    const int n = n0 + na + i * 16 + g;
                    out[((size_t)bh * NX + n) * Dc + d]     = e0;
                    out[((size_t)bh * NX + n + 8) * Dc + d] = e1;
                }
            }
        }

        __syncthreads();   // buffer handoff: all LDSM of buf[j&1] done before reuse
    }
}

extern "C" void kernel_launch(void* const* d_in, const int* in_sizes, int n_in,
                              void* d_out, int out_size)
{
    const float* Q  = (const float*)d_in[0];
    const float* K  = (const float*)d_in[1];
    const int*   sk = (const int*)d_in[2];
    const float* sg = (const float*)d_in[3];
    float* out = (float*)d_out;

    cudaFuncSetAttribute(sketch_attn_pipe,
                         cudaFuncAttributeMaxDynamicSharedMemorySize, SMEM_BYTES);

    dim3 grid(NX / BN, Dc / (NBLK * 32), Bc * Hc);   // (32, 2, 16) = 1024 CTAs
    sketch_attn_pipe<<<grid, TH, SMEM_BYTES>>>(Q, K, sk, sg, out);
}

// round 6
// speedup vs baseline: 2.9719x; 1.0759x over previous
#include <cuda_runtime.h>
#include <cuda_bf16.h>
#include <cstdint>

// Problem constants
#define Bc 2
#define Hc 8
#define Nc 2048
#define Pc 64
#define Mc 4
#define Dc 256
#define NX 4096

// Tiling: CTA holds X tile (128 x 64); loops over NBLK d-blocks of 32 d's.
// Per block: C = X(128x64) * W^T(128x64) -> 128x128, cols packed c = d'*4 + m.
#define BN 128
#define BC 128
#define NBLK 4
#define TH 256
#define ROWB 144                      // smem row stride bytes (LDSM conflict-free)
#define OFF_A 0
#define OFF_B0 (BN * ROWB)            // 18,432
#define OFF_B1 (OFF_B0 + BC * ROWB)   // 36,864
#define SMEM_BYTES (OFF_B1 + BC * ROWB)  // 55,296 B -> 2 CTAs/SM by smem

__device__ __forceinline__ uint32_t s2u(const void* p) {
    uint32_t a;
    asm("{ .reg .u64 t; cvta.to.shared.u64 t, %1; cvt.u32.u64 %0, t; }" : "=r"(a) : "l"(p));
    return a;
}
__device__ __forceinline__ uint32_t pack_bf16x2(float lo, float hi) {
    uint32_t r;
    asm("cvt.rn.bf16x2.f32 %0, %1, %2;" : "=r"(r) : "f"(hi), "f"(lo));
    return r;
}

__global__ void __launch_bounds__(TH, 2) sketch_attn_pipe2(
    const float* __restrict__ Q, const float* __restrict__ Km,
    const int* __restrict__ sk, const float* __restrict__ sgn,
    float* __restrict__ out)
{
    extern __shared__ char smem[];
    const uint32_t sb = s2u(smem);
    const int tid = threadIdx.x;

    const int bh = blockIdx.z;
    const int b  = bh >> 3;
    const int n0 = blockIdx.x * BN;
    const int dbase = blockIdx.y * (NBLK * 32);   // 128 d's per CTA

    const float* Xq = Q  + (size_t)bh * Nc * Pc;
    const float* Xk = Km + (size_t)bh * Nc * Pc;

    // ---- Fill A tile once: X rows n0..+127 (float4 -> bf16x2 pair) ----
    #pragma unroll
    for (int it = 0; it < (BN * 16) / TH; it++) {
        int i = it * TH + tid;
        int r = i >> 4, v = (i & 15) << 2;
        int gn = n0 + r;
        const float* src = (gn < Nc) ? (Xq + (size_t)gn * Pc)
                                     : (Xk + (size_t)(gn - Nc) * Pc);
        float4 x = *(const float4*)(src + v);
        *(uint2*)(smem + OFF_A + r * ROWB + v * 2) =
            make_uint2(pack_bf16x2(x.x, x.y), pack_bf16x2(x.z, x.w));
    }

    // ---- W gather into a given buffer: row c -> (m = c&3, d = d0 + c>>2) ----
    auto gatherW = [&](int d0, uint32_t off) {
        #pragma unroll 4
        for (int it = 0; it < (BC * 16) / TH; it++) {
            int i = it * TH + tid;
            int c = i >> 4, v = (i & 15) << 2;
            int m = c & 3;
            int d = d0 + (c >> 2);
            int s = sk[(b * Mc + m) * Dc + d];
            const float* src = (s < Nc) ? (Xq + (size_t)s * Pc)
                                        : (Xk + (size_t)(s - Nc) * Pc);
            float4 x = *(const float4*)(src + v);
            *(uint2*)(smem + (size_t)off + c * ROWB + v * 2) =
                make_uint2(pack_bf16x2(x.x, x.y), pack_bf16x2(x.z, x.w));
        }
    };

    gatherW(dbase, OFF_B0);
    __syncthreads();

    // ---- Warp tiling: 2 (n) x 4 (c) warps; warp tile 64 x 32 ----
    const int lane = tid & 31, warp = tid >> 5;
    const int wn = warp & 1, wc = warp >> 1;
    const int na = wn * 64, ca = wc * 32;
    const int g = lane >> 2, q = lane & 3;
    const int m0 = (q & 1) * 2;

    // LDSM lane addresses (per buffer for B).
    const uint32_t aAddr = sb + OFF_A
        + (uint32_t)(na + (lane & 15)) * ROWB + (uint32_t)(lane >> 4) * 16;
    const uint32_t bLane =
        (uint32_t)(ca + ((lane >> 4) << 3) + (lane & 7)) * ROWB
        + (uint32_t)((lane >> 3) & 1) * 16;

    // Hoisted per-thread sign coefficients: d-offset within block is fixed.
    const int dloc = wc * 8 + (q >> 1);   // + jj*2 at use site
    float sgA[4], sgB[4];
    #pragma unroll
    for (int jj = 0; jj < 4; jj++) {
        const int d = dbase + dloc + jj * 2;   // same (m0, d mod pattern) every block? no:
        (void)d;                               // signs depend only on (m, d); d varies per block.
    }

    #pragma unroll
    for (int j = 0; j < NBLK; j++) {
        // Prefetch next W block into the idle buffer (overlaps MMA + epilogue).
        if (j < NBLK - 1)
            gatherW(dbase + (j + 1) * 32, (j & 1) ? OFF_B0 : OFF_B1);

        const uint32_t bAddr = sb + ((j & 1) ? OFF_B1 : OFF_B0) + bLane;
        const int d0 = dbase + j * 32;

        float acc[4][4][4];
        #pragma unroll
        for (int i = 0; i < 4; i++)
            #pragma unroll
            for (int jj = 0; jj < 4; jj++)
                #pragma unroll
                for (int r = 0; r < 4; r++)
                    acc[i][jj][r] = 0.0f;

        // K-loop: 4 steps of k16; 4x4 m16n8k16 grid per warp.
        #pragma unroll
        for (int k = 0; k < 4; k++) {
            const uint32_t ko = (uint32_t)k * 32;
            uint32_t a[4][4];
            #pragma unroll
            for (int i = 0; i < 4; i++)
                asm volatile("ldmatrix.sync.aligned.m8n8.x4.shared.b16 {%0,%1,%2,%3}, [%4];"
                             : "=r"(a[i][0]), "=r"(a[i][1]), "=r"(a[i][2]), "=r"(a[i][3])
                             : "r"(aAddr + (uint32_t)i * 16 * ROWB + ko));
            uint32_t bb[4][2];
            #pragma unroll
            for (int p = 0; p < 2; p++)
                asm volatile("ldmatrix.sync.aligned.m8n8.x4.shared.b16 {%0,%1,%2,%3}, [%4];"
                             : "=r"(bb[2*p][0]), "=r"(bb[2*p][1]),
                               "=r"(bb[2*p+1][0]), "=r"(bb[2*p+1][1])
                             : "r"(bAddr + (uint32_t)p * 16 * ROWB + ko));
            #pragma unroll
            for (int i = 0; i < 4; i++)
                #pragma unroll
                for (int jj = 0; jj < 4; jj++)
                    asm volatile(
                        "mma.sync.aligned.m16n8k16.row.col.f32.bf16.bf16.f32 "
                        "{%0,%1,%2,%3}, {%4,%5,%6,%7}, {%8,%9}, {%0,%1,%2,%3};\n"
                        : "+f"(acc[i][jj][0]), "+f"(acc[i][jj][1]),
                          "+f"(acc[i][jj][2]), "+f"(acc[i][jj][3])
                        : "r"(a[i][0]), "r"(a[i][1]), "r"(a[i][2]), "r"(a[i][3]),
                          "r"(bb[jj][0]), "r"(bb[jj][1]));
        }

        // Epilogue: exp + signed m-reduction.
        // c0,c1 = (row g, cols 2q,2q+1); c2,c3 = (row g+8, cols 2q,2q+1).
        // Cols 2q,2q+1 share d; lane pair (q xor 1) holds the other two m's.
        #pragma unroll
        for (int jj = 0; jj < 4; jj++) {
            const int d = d0 + dloc + jj * 2;
            const float sA = sgn[m0 * Dc + d];
            const float sB = sgn[(m0 + 1) * Dc + d];
            #pragma unroll
            for (int i = 0; i < 4; i++) {
                float e0 = sA * __expf(acc[i][jj][0]) + sB * __expf(acc[i][jj][1]);
                float e1 = sA * __expf(acc[i][jj][2]) + sB * __expf(acc[i][jj][3]);
                e0 += __shfl_xor_sync(0xffffffffu, e0, 1);
                e1 += __shfl_xor_sync(0xffffffffu, e1, 1);
                if ((q & 1) == 0) {
                    const int n = n0 + na + i * 16 + g;
                    out[((size_t)bh * NX + n) * Dc + d]     = e0;
                    out[((size_t)bh * NX + n + 8) * Dc + d] = e1;
                }
            }
        }

        __syncthreads();   // buffer handoff: all LDSM of buf[j&1] done before reuse
    }
}

extern "C" void kernel_launch(void* const* d_in, const int* in_sizes, int n_in,
                              void* d_out, int out_size)
{
    const float* Q  = (const float*)d_in[0];
    const float* K  = (const float*)d_in[1];
    const int*   sk = (const int*)d_in[2];
    const float* sg = (const float*)d_in[3];
    float* out = (float*)d_out;

    cudaFuncSetAttribute(sketch_attn_pipe2,
                         cudaFuncAttributeMaxDynamicSharedMemorySize, SMEM_BYTES);

    dim3 grid(NX / BN, Dc / (NBLK * 32), Bc * Hc);   // (32, 2, 16) = 1024 CTAs
    sketch_attn_pipe2<<<grid, TH, SMEM_BYTES>>>(Q, K, sk, sg, out);
}

// round 7
// speedup vs baseline: 3.1348x; 1.0548x over previous
#include <cuda_runtime.h>
#include <cuda_bf16.h>
#include <cstdint>

// Problem constants
#define Bc 2
#define Hc 8
#define Nc 2048
#define Pc 64
#define Mc 4
#define Dc 256
#define NX 4096

// Tiling: CTA holds X tile (128 x 64); loops over NBLK d-blocks of 32 d's.
// Per block: C = X(128x64) * W^T(128x64) -> 128x128, cols packed c = d'*4 + m.
#define BN 128
#define BC 128
#define NBLK 4
#define TH 256
#define ROWB 144                      // smem row stride bytes (LDSM conflict-free)
#define OFF_A 0
#define OFF_B0 (BN * ROWB)            // 18,432
#define OFF_B1 (OFF_B0 + BC * ROWB)   // 36,864
#define SMEM_BYTES (OFF_B1 + BC * ROWB)  // 55,296 B -> 2 CTAs/SM

__device__ __forceinline__ uint32_t s2u(const void* p) {
    uint32_t a;
    asm("{ .reg .u64 t; cvta.to.shared.u64 t, %1; cvt.u32.u64 %0, t; }" : "=r"(a) : "l"(p));
    return a;
}
__device__ __forceinline__ uint32_t pack_bf16x2(float lo, float hi) {
    uint32_t r;
    asm("cvt.rn.bf16x2.f32 %0, %1, %2;" : "=r"(r) : "f"(hi), "f"(lo));
    return r;
}

__global__ void __launch_bounds__(TH, 2) sketch_attn_pipe3(
    const float* __restrict__ Q, const float* __restrict__ Km,
    const int* __restrict__ sk, const float* __restrict__ sgn,
    float* __restrict__ out)
{
    extern __shared__ char smem[];
    const uint32_t sb = s2u(smem);
    const int tid = threadIdx.x;

    const int bh = blockIdx.z;
    const int b  = bh >> 3;
    const int n0 = blockIdx.x * BN;
    const int dbase = blockIdx.y * (NBLK * 32);   // 128 d's per CTA

    const float* Xq = Q  + (size_t)bh * Nc * Pc;
    const float* Xk = Km + (size_t)bh * Nc * Pc;

    // ---- Fill A tile once: X rows n0..+127 (float4 -> bf16x2 pair) ----
    #pragma unroll
    for (int it = 0; it < (BN * 16) / TH; it++) {
        int i = it * TH + tid;
        int r = i >> 4, v = (i & 15) << 2;
        int gn = n0 + r;
        const float* src = (gn < Nc) ? (Xq + (size_t)gn * Pc)
                                     : (Xk + (size_t)(gn - Nc) * Pc);
        float4 x = *(const float4*)(src + v);
        *(uint2*)(smem + OFF_A + r * ROWB + v * 2) =
            make_uint2(pack_bf16x2(x.x, x.y), pack_bf16x2(x.z, x.w));
    }

    // ---- W gather, two-phase: batch all 8 index LDGs, then row LDG->cvt->STS ----
    auto gatherW = [&](int d0, uint32_t off) {
        int sarr[8];
        #pragma unroll
        for (int it = 0; it < 8; it++) {
            int i = it * TH + tid;
            int c = i >> 4;
            int m = c & 3;
            int d = d0 + (c >> 2);
            sarr[it] = sk[(b * Mc + m) * Dc + d];
        }
        #pragma unroll
        for (int it = 0; it < 8; it++) {
            int i = it * TH + tid;
            int c = i >> 4, v = (i & 15) << 2;
            int s = sarr[it];
            const float* src = (s < Nc) ? (Xq + (size_t)s * Pc)
                                        : (Xk + (size_t)(s - Nc) * Pc);
            float4 x = *(const float4*)(src + v);
            *(uint2*)(smem + (size_t)off + c * ROWB + v * 2) =
                make_uint2(pack_bf16x2(x.x, x.y), pack_bf16x2(x.z, x.w));
        }
    };

    gatherW(dbase, OFF_B0);
    __syncthreads();

    // ---- Warp tiling: 2 (n) x 4 (c) warps; warp tile 64 x 32 ----
    const int lane = tid & 31, warp = tid >> 5;
    const int wn = warp & 1, wc = warp >> 1;
    const int na = wn * 64, ca = wc * 32;
    const int g = lane >> 2, q = lane & 3;
    const int m0 = (q & 1) * 2;
    const int half = (q & 1) * 2;        // jj-pair base for final assembly

    // LDSM lane addresses (per buffer for B).
    const uint32_t aAddr = sb + OFF_A
        + (uint32_t)(na + (lane & 15)) * ROWB + (uint32_t)(lane >> 4) * 16;
    const uint32_t bLane =
        (uint32_t)(ca + ((lane >> 4) << 3) + (lane & 7)) * ROWB
        + (uint32_t)((lane >> 3) & 1) * 16;

    #pragma unroll
    for (int j = 0; j < NBLK; j++) {
        // Prefetch next W block into the idle buffer (overlaps MMA + epilogue).
        if (j < NBLK - 1)
            gatherW(dbase + (j + 1) * 32, (j & 1) ? OFF_B0 : OFF_B1);

        const uint32_t bAddr = sb + ((j & 1) ? OFF_B1 : OFF_B0) + bLane;
        const int d0 = dbase + j * 32;

        float acc[4][4][4];
        #pragma unroll
        for (int i = 0; i < 4; i++)
            #pragma unroll
            for (int jj = 0; jj < 4; jj++)
                #pragma unroll
                for (int r = 0; r < 4; r++)
                    acc[i][jj][r] = 0.0f;

        // K-loop: 4 steps of k16; 4x4 m16n8k16 grid per warp.
        #pragma unroll
        for (int k = 0; k < 4; k++) {
            const uint32_t ko = (uint32_t)k * 32;
            uint32_t a[4][4];
            #pragma unroll
            for (int i = 0; i < 4; i++)
                asm volatile("ldmatrix.sync.aligned.m8n8.x4.shared.b16 {%0,%1,%2,%3}, [%4];"
                             : "=r"(a[i][0]), "=r"(a[i][1]), "=r"(a[i][2]), "=r"(a[i][3])
                             : "r"(aAddr + (uint32_t)i * 16 * ROWB + ko));
            uint32_t bb[4][2];
            #pragma unroll
            for (int p = 0; p < 2; p++)
                asm volatile("ldmatrix.sync.aligned.m8n8.x4.shared.b16 {%0,%1,%2,%3}, [%4];"
                             : "=r"(bb[2*p][0]), "=r"(bb[2*p][1]),
                               "=r"(bb[2*p+1][0]), "=r"(bb[2*p+1][1])
                             : "r"(bAddr + (uint32_t)p * 16 * ROWB + ko));
            #pragma unroll
            for (int i = 0; i < 4; i++)
                #pragma unroll
                for (int jj = 0; jj < 4; jj++)
                    asm volatile(
                        "mma.sync.aligned.m16n8k16.row.col.f32.bf16.bf16.f32 "
                        "{%0,%1,%2,%3}, {%4,%5,%6,%7}, {%8,%9}, {%0,%1,%2,%3};\n"
                        : "+f"(acc[i][jj][0]), "+f"(acc[i][jj][1]),
                          "+f"(acc[i][jj][2]), "+f"(acc[i][jj][3])
                        : "r"(a[i][0]), "r"(a[i][1]), "r"(a[i][2]), "r"(a[i][3]),
                          "r"(bb[jj][0]), "r"(bb[jj][1]));
        }

        // ---- Epilogue: exp + signed m-reduce (xor 1), then d-assembly (xor 2)
        //      so each lane emits one sector-exact float4. ----
        // After xor(1): every lane holds E(row g, d) in e0[jj], E(row g+8, d) in
        // e1[jj], d = d0 + wc*8 + jj*2 + (q>>1), duplicated across the q&1 pair.
        // xor(2) swaps even<->odd d's; selects assemble 4 consecutive d's.
        #pragma unroll
        for (int i = 0; i < 4; i++) {
            float e0[4], e1[4];
            #pragma unroll
            for (int jj = 0; jj < 4; jj++) {
                const int d = d0 + wc * 8 + jj * 2 + (q >> 1);
                const float sA = sgn[m0 * Dc + d];
                const float sB = sgn[(m0 + 1) * Dc + d];
                float t0 = sA * __expf(acc[i][jj][0]) + sB * __expf(acc[i][jj][1]);
                float t1 = sA * __expf(acc[i][jj][2]) + sB * __expf(acc[i][jj][3]);
                t0 += __shfl_xor_sync(0xffffffffu, t0, 1);
                t1 += __shfl_xor_sync(0xffffffffu, t1, 1);
                e0[jj] = t0; e1[jj] = t1;
            }
            float f0[4], f1[4];
            #pragma unroll
            for (int jj = 0; jj < 4; jj++) {
                f0[jj] = __shfl_xor_sync(0xffffffffu, e0[jj], 2);
                f1[jj] = __shfl_xor_sync(0xffffffffu, e1[jj], 2);
            }
            const bool lo = (q < 2);
            float4 v;
            v.x = lo ? e0[half]     : f1[half];
            v.y = lo ? f0[half]     : e1[half];
            v.z = lo ? e0[half + 1] : f1[half + 1];
            v.w = lo ? f0[half + 1] : e1[half + 1];
            const int n = n0 + na + i * 16 + g + (lo ? 0 : 8);
            const int dcol = d0 + wc * 8 + (q & 1) * 4;
            *(float4*)(out + ((size_t)bh * NX + n) * Dc + dcol) = v;
        }

        __syncthreads();   // buffer handoff: all LDSM of buf[j&1] done before reuse
    }
}

extern "C" void kernel_launch(void* const* d_in, const int* in_sizes, int n_in,
                              void* d_out, int out_size)
{
    const float* Q  = (const float*)d_in[0];
    const float* K  = (const float*)d_in[1];
    const int*   sk = (const int*)d_in[2];
    const float* sg = (const float*)d_in[3];
    float* out = (float*)d_out;

    cudaFuncSetAttribute(sketch_attn_pipe3,
                         cudaFuncAttributeMaxDynamicSharedMemorySize, SMEM_BYTES);

    dim3 grid(NX / BN, Dc / (NBLK * 32), Bc * Hc);   // (32, 2, 16) = 1024 CTAs
    sketch_attn_pipe3<<<grid, TH, SMEM_BYTES>>>(Q, K, sk, sg, out);
}